// round 14
// baseline (speedup 1.0000x reference)
#include <cuda_runtime.h>
#include <cuda_fp16.h>
#include <cstdint>

#define NPTS 40000
#define NSAMP 32
#define STOT (NPTS * NSAMP)     // 1,280,000
#define C0IN 38
#define C1 64
#define C2 64
#define C3 128
#define BNEPS 1e-5f
#define BLK 256
#define NWARP 8
#define TM 128
#define NT1 (STOT / TM)         // 10000 tiles
#define TILEH (TM * 64)         // halves per staging tile (16 KB)
#define S2 4                    // k_l2 cp.async pipeline depth

// ---------------- scratch ---------------------------------------------------
__device__ __align__(16) float g_A[NPTS * C1];
__device__ __align__(16) float g_B[NPTS * C1];
__device__ __align__(16) __half2 g_Ah[NPTS * 32];   // fp16 copies for l0stats only
__device__ __align__(16) __half2 g_Bh[NPTS * 32];
__device__ __align__(16) uint4 g_y1f[(size_t)NT1 * 1024];   // fragment-linear fp16 y1
__device__ __align__(16) float g_pmax[NPTS * C3];           // sign-folded extrema

__device__ float g_sum0[C1], g_sq0[C1];
__device__ float g_sum1[C2], g_sq1[C2];
__device__ float g_sum2[C3], g_sq2[C3];

// ---------------- helpers ---------------------------------------------------
__device__ __forceinline__ void ldsm4(uint32_t* a, const __half* p) {
    uint32_t sa = (uint32_t)__cvta_generic_to_shared(p);
    asm volatile("ldmatrix.sync.aligned.m8n8.x4.shared.b16 {%0,%1,%2,%3}, [%4];"
                 : "=r"(a[0]), "=r"(a[1]), "=r"(a[2]), "=r"(a[3]) : "r"(sa));
}
__device__ __forceinline__ void mma16(float* d, const uint32_t* a, const uint32_t* b) {
    asm volatile(
        "mma.sync.aligned.m16n8k16.row.col.f32.f16.f16.f32 "
        "{%0,%1,%2,%3}, {%4,%5,%6,%7}, {%8,%9}, {%0,%1,%2,%3};"
        : "+f"(d[0]), "+f"(d[1]), "+f"(d[2]), "+f"(d[3])
        : "r"(a[0]), "r"(a[1]), "r"(a[2]), "r"(a[3]), "r"(b[0]), "r"(b[1]));
}
__device__ __forceinline__ uint32_t packh2(float x, float y) {
    __half2 h = __floats2half2_rn(x, y);
    return *reinterpret_cast<uint32_t*>(&h);
}
__device__ __forceinline__ uint32_t hfma2relu(uint32_t a, uint32_t y, uint32_t c) {
    __half2 r = __hfma2_relu(*reinterpret_cast<__half2*>(&a),
                             *reinterpret_cast<__half2*>(&y),
                             *reinterpret_cast<__half2*>(&c));
    return *reinterpret_cast<uint32_t*>(&r);
}
__device__ __forceinline__ void cpa16(uint4* dst, const uint4* src) {
    uint32_t d = (uint32_t)__cvta_generic_to_shared(dst);
    asm volatile("cp.async.cg.shared.global [%0], [%1], 16;" :: "r"(d), "l"(src) : "memory");
}

// ---------------- k_pre: zero stats + passthrough copy + A/B precompute ----
__global__ void k_pre(const float* __restrict__ center,
                      const float* __restrict__ normal,
                      const float* __restrict__ feature,
                      const int* __restrict__ offset,
                      const float* __restrict__ W0,
                      const float* __restrict__ b0,
                      float* __restrict__ out, int doCopy) {
    if (blockIdx.x == 0) {
        int t = threadIdx.x;
        if (t < C1) { g_sum0[t] = 0.f; g_sq0[t] = 0.f; g_sum1[t] = 0.f; g_sq1[t] = 0.f; }
        if (t < C3) { g_sum2[t] = 0.f; g_sq2[t] = 0.f; }
    }
    if (doCopy) {
        int i = blockIdx.x * blockDim.x + threadIdx.x;
        int stride = gridDim.x * blockDim.x;
        for (; i < 2 * NPTS * 3; i += stride) {
            out[i] = (i < NPTS * 3) ? center[i] : normal[i - NPTS * 3];
        }
        if (blockIdx.x == 0 && threadIdx.x == 0) {
            out[2 * NPTS * 3 + NPTS * C3] = (float)offset[0];
        }
    }

    __shared__ __align__(16) float Wt[C0IN * C1];
    __shared__ float xs[NWARP][C0IN];
    int tid = threadIdx.x;
    for (int i = tid; i < C0IN * C1; i += BLK) {
        int o = i / C0IN, c = i % C0IN;
        Wt[c * C1 + o] = W0[i];
    }
    __syncthreads();
    int w = tid >> 5, lane = tid & 31;
    int o0 = 2 * lane;
    float bias0 = b0[o0], bias1 = b0[o0 + 1];
    int wg = blockIdx.x * NWARP + w, nW = gridDim.x * NWARP;
    for (int n = wg; n < NPTS; n += nW) {
        {
            float v;
            if (lane < 3)      v = center[n * 3 + lane];
            else if (lane < 6) v = normal[n * 3 + lane - 3];
            else               v = feature[n * 32 + lane - 6];
            xs[w][lane] = v;
            if (lane < C0IN - 32) xs[w][32 + lane] = feature[n * 32 + 26 + lane];
        }
        __syncwarp();
        float a0 = 0.f, a1 = 0.f, bp0 = 0.f, bp1 = 0.f;
        #pragma unroll
        for (int c = 0; c < C0IN; ++c) {
            float2 wv = *(const float2*)&Wt[c * C1 + o0];
            float x = xs[w][c];
            a0 += wv.x * x; a1 += wv.y * x;
            if (c < 3) { bp0 += wv.x * x; bp1 += wv.y * x; }
        }
        float A0 = a0 + bias0, A1 = a1 + bias1;
        *(float2*)&g_A[n * C1 + o0] = make_float2(A0, A1);
        *(float2*)&g_B[n * C1 + o0] = make_float2(bp0, bp1);
        g_Ah[n * 32 + lane] = __floats2half2_rn(A0, A1);
        g_Bh[n * 32 + lane] = __floats2half2_rn(bp0, bp1);
        __syncwarp();
    }
}

// ---------------- layer-0 stats on fp16 copies (half the L2 traffic) -------
__global__ void k_l0stats(const int* __restrict__ gidx) {
    __shared__ float sS[C1], sQ[C1];
    int tid = threadIdx.x;
    if (tid < C1) { sS[tid] = 0.f; sQ[tid] = 0.f; }
    __syncthreads();
    int w = tid >> 5, lane = tid & 31;
    float s0 = 0.f, s1 = 0.f, q0 = 0.f, q1 = 0.f;
    int wg = blockIdx.x * NWARP + w, nW = gridDim.x * NWARP;
    for (int n = wg; n < NPTS; n += nW) {
        float2 bv = __half22float2(g_Bh[n * 32 + lane]);
        int js = gidx[n * NSAMP + lane];
        #pragma unroll
        for (int s = 0; s < NSAMP; ++s) {
            int j = __shfl_sync(0xffffffffu, js, s);
            float2 av = __half22float2(g_Ah[j * 32 + lane]);
            float y0 = av.x - bv.x, y1v = av.y - bv.y;
            s0 += y0; s1 += y1v; q0 += y0 * y0; q1 += y1v * y1v;
        }
    }
    int c0 = 2 * lane;
    atomicAdd(&sS[c0], s0); atomicAdd(&sS[c0 + 1], s1);
    atomicAdd(&sQ[c0], q0); atomicAdd(&sQ[c0 + 1], q1);
    __syncthreads();
    if (tid < C1) { atomicAdd(&g_sum0[tid], sS[tid]); atomicAdd(&g_sq0[tid], sQ[tid]); }
}

// ---------------- coalesced fp32 gather staging (R7-proven) ----------------
__device__ __forceinline__ void stage1(__half* __restrict__ Xb, int tile, int w, int lane,
                                       const int* __restrict__ gidx,
                                       float4 a4, float4 c4) {
    int ch = lane & 15, hw = lane >> 4;
    int jreg = gidx[tile * TM + w * 16 + ch];
    int n = tile * 4 + (w >> 1);
    float4 bv = *(const float4*)&g_B[n * C1 + ch * 4];
    #pragma unroll
    for (int i = 0; i < 8; ++i) {
        int r = w * 16 + i * 2 + hw;
        int j = __shfl_sync(0xffffffffu, jreg, i * 2 + hw);
        float4 av = *(const float4*)&g_A[(size_t)j * C1 + ch * 4];
        float x0 = fmaxf(0.f, fmaf(a4.x, av.x - bv.x, c4.x));
        float x1 = fmaxf(0.f, fmaf(a4.y, av.y - bv.y, c4.y));
        float x2 = fmaxf(0.f, fmaf(a4.z, av.z - bv.z, c4.z));
        float x3 = fmaxf(0.f, fmaf(a4.w, av.w - bv.w, c4.w));
        uint32_t u0 = packh2(x0, x1), u1 = packh2(x2, x3);
        *(uint2*)(Xb + r * 64 + (((ch >> 1) ^ (r & 7)) << 3) + (ch & 1) * 4) = make_uint2(u0, u1);
    }
}

// ---------------- layer1: fin0 inline; 8 warps, warp tile 32x32 ------------
__global__ void __launch_bounds__(256, 2)
k_l1(const int* __restrict__ gidx, const float* __restrict__ W1,
     const float* __restrict__ g0, const float* __restrict__ be0) {
    extern __shared__ __align__(16) __half X[];   // [2][TILEH]
    __shared__ float aS[C1], cS[C1];
    int tid = threadIdx.x;
    if (tid < C1) {
        float inv = 1.f / (float)STOT;
        float mean = g_sum0[tid] * inv;
        float var = g_sq0[tid] * inv - mean * mean;
        float a = g0[tid] * rsqrtf(var + BNEPS);
        aS[tid] = a;
        cS[tid] = fmaf(-a, mean, be0[tid]);
    }
    int w = tid >> 5, lane = tid & 31;
    int g = lane >> 2, t = lane & 3;
    int wm = w >> 1, wn = w & 1;
    int sub = lane >> 3, ir = lane & 7;
    int rowoff = (sub & 1) * 8 + ir;
    int csel = sub >> 1;
    uint32_t Bf[4][4][2];
    #pragma unroll
    for (int nf = 0; nf < 4; ++nf)
        #pragma unroll
        for (int kf = 0; kf < 4; ++kf) {
            int n = wn * 32 + nf * 8 + g;
            const float* wr = W1 + n * C1 + kf * 16;
            Bf[nf][kf][0] = packh2(wr[2 * t], wr[2 * t + 1]);
            Bf[nf][kf][1] = packh2(wr[8 + 2 * t], wr[8 + 2 * t + 1]);
        }
    float sum[8] = {0}, sq[8] = {0};
    __syncthreads();
    int ch = lane & 15;
    float4 a4 = *(const float4*)&aS[ch * 4];
    float4 c4 = *(const float4*)&cS[ch * 4];

    int tile = blockIdx.x, buf = 0;
    stage1(X, tile, w, lane, gidx, a4, c4);
    for (; tile < NT1; tile += gridDim.x, buf ^= 1) {
        __syncthreads();
        int nxt = tile + gridDim.x;
        if (nxt < NT1) stage1(X + (buf ^ 1) * TILEH, nxt, w, lane, gidx, a4, c4);
        const __half* Xb = X + buf * TILEH;
        #pragma unroll
        for (int mf = 0; mf < 2; ++mf) {
            int rb = wm * 32 + mf * 16;
            float acc[4][4];
            #pragma unroll
            for (int nf = 0; nf < 4; ++nf)
                #pragma unroll
                for (int e = 0; e < 4; ++e) acc[nf][e] = 0.f;
            #pragma unroll
            for (int kf = 0; kf < 4; ++kf) {
                uint32_t Af[4];
                ldsm4(Af, Xb + (rb + rowoff) * 64 + (((2 * kf + csel) ^ ir) << 3));
                #pragma unroll
                for (int nf = 0; nf < 4; ++nf) mma16(acc[nf], Af, Bf[nf][kf]);
            }
            #pragma unroll
            for (int q = 0; q < 2; ++q) {
                uint4 pv;
                pv.x = packh2(acc[2 * q][0], acc[2 * q][1]);
                pv.y = packh2(acc[2 * q][2], acc[2 * q][3]);
                pv.z = packh2(acc[2 * q + 1][0], acc[2 * q + 1][1]);
                pv.w = packh2(acc[2 * q + 1][2], acc[2 * q + 1][3]);
                g_y1f[(size_t)tile * 1024 + w * 128 + mf * 64 + q * 32 + lane] = pv;
            }
            #pragma unroll
            for (int nf = 0; nf < 4; ++nf) {
                sum[nf * 2 + 0] += acc[nf][0] + acc[nf][2];
                sum[nf * 2 + 1] += acc[nf][1] + acc[nf][3];
                sq[nf * 2 + 0] += acc[nf][0] * acc[nf][0] + acc[nf][2] * acc[nf][2];
                sq[nf * 2 + 1] += acc[nf][1] * acc[nf][1] + acc[nf][3] * acc[nf][3];
            }
        }
    }
    #pragma unroll
    for (int sl = 0; sl < 8; ++sl) {
        float s = sum[sl], q = sq[sl];
        s += __shfl_xor_sync(~0u, s, 4);  q += __shfl_xor_sync(~0u, q, 4);
        s += __shfl_xor_sync(~0u, s, 8);  q += __shfl_xor_sync(~0u, q, 8);
        s += __shfl_xor_sync(~0u, s, 16); q += __shfl_xor_sync(~0u, q, 16);
        if (g == 0) {
            int col = wn * 32 + (sl >> 1) * 8 + 2 * t + (sl & 1);
            atomicAdd(&g_sum1[col], s);
            atomicAdd(&g_sq1[col], q);
        }
    }
}

// ---------------- layer2: 3 blocks/SM; warp tile 128x16 (nf=2) -------------
// cp.async ring; fragments straight from smem; BN1 coeffs from smem per kf.
__global__ void __launch_bounds__(256, 3)
k_l2(const float* __restrict__ W2,
     const float* __restrict__ g1, const float* __restrict__ be1,
     const float* __restrict__ g2) {
    extern __shared__ __align__(16) uint4 Ys[];   // [S2][1024]
    __shared__ uint32_t aH[32], cH[32];           // half2-packed BN1 coefficients
    int tid = threadIdx.x;
    if (tid < 32) {
        float inv = 1.f / (float)STOT;
        int c0i = 2 * tid, c1i = 2 * tid + 1;
        float m0 = g_sum1[c0i] * inv, m1 = g_sum1[c1i] * inv;
        float v0 = g_sq1[c0i] * inv - m0 * m0, v1 = g_sq1[c1i] * inv - m1 * m1;
        float a0 = g1[c0i] * rsqrtf(v0 + BNEPS), a1 = g1[c1i] * rsqrtf(v1 + BNEPS);
        aH[tid] = packh2(a0, a1);
        cH[tid] = packh2(fmaf(-a0, m0, be1[c0i]), fmaf(-a1, m1, be1[c1i]));
    }
    int w = tid >> 5, lane = tid & 31;
    int g = lane >> 2, t = lane & 3;
    // warp w owns cols w*16 .. w*16+15, ALL 128 rows
    uint32_t Bf[2][4][2];
    #pragma unroll
    for (int nf = 0; nf < 2; ++nf) {
        int n = w * 16 + nf * 8 + g;
        float s = (g2[n] < 0.f) ? -1.f : 1.f;
        #pragma unroll
        for (int kf = 0; kf < 4; ++kf) {
            const float* wr = W2 + n * C2 + kf * 16;
            Bf[nf][kf][0] = packh2(s * wr[2 * t], s * wr[2 * t + 1]);
            Bf[nf][kf][1] = packh2(s * wr[8 + 2 * t], s * wr[8 + 2 * t + 1]);
        }
    }
    float sum[4] = {0}, sq[4] = {0};
    __syncthreads();

    #pragma unroll
    for (int s = 0; s < S2 - 1; ++s) {
        int tl = blockIdx.x + s * gridDim.x;
        if (tl < NT1) {
            #pragma unroll
            for (int i2 = 0; i2 < 4; ++i2) {
                int u = tid + i2 * 256;
                cpa16(&Ys[s * 1024 + u], g_y1f + (size_t)tl * 1024 + u);
            }
        }
        asm volatile("cp.async.commit_group;" ::: "memory");
    }

    int it = 0;
    for (int tile = blockIdx.x; tile < NT1; tile += gridDim.x, ++it) {
        asm volatile("cp.async.wait_group %0;" :: "n"(S2 - 2));
        __syncthreads();
        int nt = tile + (S2 - 1) * gridDim.x;
        int nb = (it + S2 - 1) & (S2 - 1);
        if (nt < NT1) {
            #pragma unroll
            for (int i2 = 0; i2 < 4; ++i2) {
                int u = tid + i2 * 256;
                cpa16(&Ys[nb * 1024 + u], g_y1f + (size_t)nt * 1024 + u);
            }
        }
        asm volatile("cp.async.commit_group;" ::: "memory");

        const uint4* base = Ys + (it & (S2 - 1)) * 1024 + lane;
        float mxx[4][4];
        #pragma unroll
        for (int ps = 0; ps < 4; ++ps)
            #pragma unroll
            for (int sl = 0; sl < 4; ++sl) mxx[ps][sl] = -1e30f;
        #pragma unroll
        for (int mf = 0; mf < 8; ++mf) {      // all 8 row-16 blocks
            int rowpart = ((mf >> 1) << 8) + ((mf & 1) << 6);
            uint4 pv[4];
            #pragma unroll
            for (int kf = 0; kf < 4; ++kf)
                pv[kf] = base[rowpart + ((kf >> 1) << 7) + ((kf & 1) << 5)];
            float acc[2][4];
            #pragma unroll
            for (int nf = 0; nf < 2; ++nf)
                #pragma unroll
                for (int e = 0; e < 4; ++e) acc[nf][e] = 0.f;
            #pragma unroll
            for (int kf = 0; kf < 4; ++kf) {
                uint32_t a0 = aH[kf * 8 + t], c0 = cH[kf * 8 + t];
                uint32_t a1 = aH[kf * 8 + t + 4], c1 = cH[kf * 8 + t + 4];
                uint32_t Af[4];
                Af[0] = hfma2relu(a0, pv[kf].x, c0);
                Af[1] = hfma2relu(a0, pv[kf].y, c0);
                Af[2] = hfma2relu(a1, pv[kf].z, c1);
                Af[3] = hfma2relu(a1, pv[kf].w, c1);
                mma16(acc[0], Af, Bf[0][kf]);
                mma16(acc[1], Af, Bf[1][kf]);
            }
            int ps = mf >> 1;
            #pragma unroll
            for (int nf = 0; nf < 2; ++nf) {
                sum[nf * 2 + 0] += acc[nf][0] + acc[nf][2];
                sum[nf * 2 + 1] += acc[nf][1] + acc[nf][3];
                sq[nf * 2 + 0] += acc[nf][0] * acc[nf][0] + acc[nf][2] * acc[nf][2];
                sq[nf * 2 + 1] += acc[nf][1] * acc[nf][1] + acc[nf][3] * acc[nf][3];
                mxx[ps][nf * 2 + 0] = fmaxf(mxx[ps][nf * 2 + 0], fmaxf(acc[nf][0], acc[nf][2]));
                mxx[ps][nf * 2 + 1] = fmaxf(mxx[ps][nf * 2 + 1], fmaxf(acc[nf][1], acc[nf][3]));
            }
        }
        #pragma unroll
        for (int ps = 0; ps < 4; ++ps)
            #pragma unroll
            for (int sl = 0; sl < 4; ++sl) {
                float mx = mxx[ps][sl];
                mx = fmaxf(mx, __shfl_xor_sync(~0u, mx, 4));
                mx = fmaxf(mx, __shfl_xor_sync(~0u, mx, 8));
                mx = fmaxf(mx, __shfl_xor_sync(~0u, mx, 16));
                if (g == 0) {
                    int col = w * 16 + (sl >> 1) * 8 + 2 * t + (sl & 1);
                    int n = tile * 4 + ps;
                    g_pmax[n * C3 + col] = mx;
                }
            }
    }
    #pragma unroll
    for (int sl = 0; sl < 4; ++sl) {
        float s = sum[sl], q = sq[sl];
        s += __shfl_xor_sync(~0u, s, 4);  q += __shfl_xor_sync(~0u, q, 4);
        s += __shfl_xor_sync(~0u, s, 8);  q += __shfl_xor_sync(~0u, q, 8);
        s += __shfl_xor_sync(~0u, s, 16); q += __shfl_xor_sync(~0u, q, 16);
        if (g == 0) {
            int col = w * 16 + (sl >> 1) * 8 + 2 * t + (sl & 1);
            if (g2[col] < 0.f) s = -s;   // un-fold sign for the true sum
            atomicAdd(&g_sum2[col], s);
            atomicAdd(&g_sq2[col], q);
        }
    }
}

// ---------------- epilogue: fin2 inline + BN2+relu on sign-folded max ------
__global__ void k_poolapply(float* __restrict__ out,
                            const float* __restrict__ g2,
                            const float* __restrict__ be2) {
    __shared__ float a2S[C3], c2S[C3];
    int tid = threadIdx.x;
    if (tid < C3) {
        float inv = 1.f / (float)STOT;
        float mean = g_sum2[tid] * inv;
        float var = g_sq2[tid] * inv - mean * mean;
        float a = g2[tid] * rsqrtf(var + BNEPS);
        a2S[tid] = fabsf(a);
        c2S[tid] = fmaf(-a, mean, be2[tid]);
    }
    __syncthreads();
    int idx = blockIdx.x * blockDim.x + tid;
    if (idx >= NPTS * (C3 / 4)) return;
    int n = idx >> 5, cg = (idx & 31) * 4;
    float4 a = *(const float4*)&a2S[cg];
    float4 c = *(const float4*)&c2S[cg];
    float4 m = *(const float4*)&g_pmax[n * C3 + cg];
    float4 o;
    o.x = fmaxf(0.f, fmaf(a.x, m.x, c.x));
    o.y = fmaxf(0.f, fmaf(a.y, m.y, c.y));
    o.z = fmaxf(0.f, fmaf(a.z, m.z, c.z));
    o.w = fmaxf(0.f, fmaf(a.w, m.w, c.w));
    *(float4*)&out[(size_t)n * C3 + cg] = o;
}

// ---------------- host entry ------------------------------------------------
extern "C" void kernel_launch(void* const* d_in, const int* in_sizes, int n_in,
                              void* d_out, int out_size) {
    const float* center  = (const float*)d_in[0];
    const float* normal  = (const float*)d_in[1];
    const float* feature = (const float*)d_in[2];
    const int*   offset  = (const int*)d_in[3];
    const int*   gidx    = (const int*)d_in[4];
    const float* W0 = (const float*)d_in[5];
    const float* b0 = (const float*)d_in[6];
    const float* g0 = (const float*)d_in[7];
    const float* be0 = (const float*)d_in[8];
    const float* W1 = (const float*)d_in[9];
    const float* g1 = (const float*)d_in[11];
    const float* be1 = (const float*)d_in[12];
    const float* W2 = (const float*)d_in[13];
    const float* g2 = (const float*)d_in[15];
    const float* be2 = (const float*)d_in[16];

    float* out = (float*)d_out;
    bool full = (out_size >= 2 * NPTS * 3 + NPTS * C3 + 1);
    float* featBase = full ? out + 2 * NPTS * 3 : out;

    const int SMX = 2 * TILEH * 2;       // 32 KB (k_l1 double buffer)
    const int SM2 = S2 * 1024 * 16;      // 64 KB (k_l2 cp.async ring)
    cudaFuncSetAttribute(k_l2, cudaFuncAttributeMaxDynamicSharedMemorySize, SM2);

    k_pre<<<296, BLK>>>(center, normal, feature, offset, W0, b0, out, full ? 1 : 0);
    k_l0stats<<<1184, BLK>>>(gidx);
    k_l1<<<296, 256, SMX>>>(gidx, W1, g0, be0);
    k_l2<<<444, 256, SM2>>>(W2, g1, be1, g2);
    k_poolapply<<<5000, BLK>>>(featBase, g2, be2);
}

// round 15
// speedup vs baseline: 1.0588x; 1.0588x over previous
#include <cuda_runtime.h>
#include <cuda_fp16.h>
#include <cstdint>

#define NPTS 40000
#define NSAMP 32
#define STOT (NPTS * NSAMP)     // 1,280,000
#define C0IN 38
#define C1 64
#define C2 64
#define C3 128
#define BNEPS 1e-5f
#define BLK 256
#define NWARP 8
#define TM 128
#define NT1 (STOT / TM)         // 10000 tiles
#define TILEH (TM * 64)         // halves per staging tile (16 KB)
#define S2 4                    // k_l2 cp.async pipeline depth

// ---------------- scratch ---------------------------------------------------
__device__ __align__(16) __half2 g_Ah[NPTS * 32];   // per-point A (fp16)
__device__ __align__(16) __half2 g_Bh[NPTS * 32];   // per-point B (fp16)
__device__ __align__(16) uint4 g_y1f[(size_t)NT1 * 1024];   // fragment-linear fp16 y1
__device__ __align__(16) float g_pmax[NPTS * C3];           // sign-folded extrema

__device__ float g_sum0[C1], g_sq0[C1];
__device__ float g_sum1[C2], g_sq1[C2];
__device__ float g_sum2[C3], g_sq2[C3];

// ---------------- helpers ---------------------------------------------------
__device__ __forceinline__ void ldsm4(uint32_t* a, const __half* p) {
    uint32_t sa = (uint32_t)__cvta_generic_to_shared(p);
    asm volatile("ldmatrix.sync.aligned.m8n8.x4.shared.b16 {%0,%1,%2,%3}, [%4];"
                 : "=r"(a[0]), "=r"(a[1]), "=r"(a[2]), "=r"(a[3]) : "r"(sa));
}
__device__ __forceinline__ void mma16(float* d, const uint32_t* a, const uint32_t* b) {
    asm volatile(
        "mma.sync.aligned.m16n8k16.row.col.f32.f16.f16.f32 "
        "{%0,%1,%2,%3}, {%4,%5,%6,%7}, {%8,%9}, {%0,%1,%2,%3};"
        : "+f"(d[0]), "+f"(d[1]), "+f"(d[2]), "+f"(d[3])
        : "r"(a[0]), "r"(a[1]), "r"(a[2]), "r"(a[3]), "r"(b[0]), "r"(b[1]));
}
__device__ __forceinline__ uint32_t packh2(float x, float y) {
    __half2 h = __floats2half2_rn(x, y);
    return *reinterpret_cast<uint32_t*>(&h);
}
__device__ __forceinline__ uint32_t hfma2relu(uint32_t a, uint32_t y, uint32_t c) {
    __half2 r = __hfma2_relu(*reinterpret_cast<__half2*>(&a),
                             *reinterpret_cast<__half2*>(&y),
                             *reinterpret_cast<__half2*>(&c));
    return *reinterpret_cast<uint32_t*>(&r);
}
__device__ __forceinline__ uint32_t hsub2u(uint32_t a, uint32_t b) {
    __half2 r = __hsub2(*reinterpret_cast<__half2*>(&a), *reinterpret_cast<__half2*>(&b));
    return *reinterpret_cast<uint32_t*>(&r);
}
__device__ __forceinline__ void cpa16(uint4* dst, const uint4* src) {
    uint32_t d = (uint32_t)__cvta_generic_to_shared(dst);
    asm volatile("cp.async.cg.shared.global [%0], [%1], 16;" :: "r"(d), "l"(src) : "memory");
}

// ---------------- k_pre: zero stats + passthrough copy + A/B precompute ----
__global__ void k_pre(const float* __restrict__ center,
                      const float* __restrict__ normal,
                      const float* __restrict__ feature,
                      const int* __restrict__ offset,
                      const float* __restrict__ W0,
                      const float* __restrict__ b0,
                      float* __restrict__ out, int doCopy) {
    if (blockIdx.x == 0) {
        int t = threadIdx.x;
        if (t < C1) { g_sum0[t] = 0.f; g_sq0[t] = 0.f; g_sum1[t] = 0.f; g_sq1[t] = 0.f; }
        if (t < C3) { g_sum2[t] = 0.f; g_sq2[t] = 0.f; }
    }
    if (doCopy) {
        int i = blockIdx.x * blockDim.x + threadIdx.x;
        int stride = gridDim.x * blockDim.x;
        for (; i < 2 * NPTS * 3; i += stride) {
            out[i] = (i < NPTS * 3) ? center[i] : normal[i - NPTS * 3];
        }
        if (blockIdx.x == 0 && threadIdx.x == 0) {
            out[2 * NPTS * 3 + NPTS * C3] = (float)offset[0];
        }
    }

    __shared__ __align__(16) float Wt[C0IN * C1];
    __shared__ float xs[NWARP][C0IN];
    int tid = threadIdx.x;
    for (int i = tid; i < C0IN * C1; i += BLK) {
        int o = i / C0IN, c = i % C0IN;
        Wt[c * C1 + o] = W0[i];
    }
    __syncthreads();
    int w = tid >> 5, lane = tid & 31;
    int o0 = 2 * lane;
    float bias0 = b0[o0], bias1 = b0[o0 + 1];
    int wg = blockIdx.x * NWARP + w, nW = gridDim.x * NWARP;
    for (int n = wg; n < NPTS; n += nW) {
        {
            float v;
            if (lane < 3)      v = center[n * 3 + lane];
            else if (lane < 6) v = normal[n * 3 + lane - 3];
            else               v = feature[n * 32 + lane - 6];
            xs[w][lane] = v;
            if (lane < C0IN - 32) xs[w][32 + lane] = feature[n * 32 + 26 + lane];
        }
        __syncwarp();
        float a0 = 0.f, a1 = 0.f, bp0 = 0.f, bp1 = 0.f;
        #pragma unroll
        for (int c = 0; c < C0IN; ++c) {
            float2 wv = *(const float2*)&Wt[c * C1 + o0];
            float x = xs[w][c];
            a0 += wv.x * x; a1 += wv.y * x;
            if (c < 3) { bp0 += wv.x * x; bp1 += wv.y * x; }
        }
        g_Ah[n * 32 + lane] = __floats2half2_rn(a0 + bias0, a1 + bias1);
        g_Bh[n * 32 + lane] = __floats2half2_rn(bp0, bp1);
        __syncwarp();
    }
}

// ---------------- layer-0 stats on fp16 A/B --------------------------------
__global__ void k_l0stats(const int* __restrict__ gidx) {
    __shared__ float sS[C1], sQ[C1];
    int tid = threadIdx.x;
    if (tid < C1) { sS[tid] = 0.f; sQ[tid] = 0.f; }
    __syncthreads();
    int w = tid >> 5, lane = tid & 31;
    float s0 = 0.f, s1 = 0.f, q0 = 0.f, q1 = 0.f;
    int wg = blockIdx.x * NWARP + w, nW = gridDim.x * NWARP;
    for (int n = wg; n < NPTS; n += nW) {
        float2 bv = __half22float2(g_Bh[n * 32 + lane]);
        int js = gidx[n * NSAMP + lane];
        #pragma unroll
        for (int s = 0; s < NSAMP; ++s) {
            int j = __shfl_sync(0xffffffffu, js, s);
            float2 av = __half22float2(g_Ah[j * 32 + lane]);
            float y0 = av.x - bv.x, y1v = av.y - bv.y;
            s0 += y0; s1 += y1v; q0 += y0 * y0; q1 += y1v * y1v;
        }
    }
    int c0 = 2 * lane;
    atomicAdd(&sS[c0], s0); atomicAdd(&sS[c0 + 1], s1);
    atomicAdd(&sQ[c0], q0); atomicAdd(&sQ[c0 + 1], q1);
    __syncthreads();
    if (tid < C1) { atomicAdd(&g_sum0[tid], sS[tid]); atomicAdd(&g_sq0[tid], sQ[tid]); }
}

// ---------------- fp16 half2-domain gather staging -------------------------
// lane = (hw=lane>>3, ch=lane&7): ch -> 16B chunk of the 128B fp16 row.
// 8 lanes share one A-row (1 line); BN0 fully in half2: hfma2_relu(a, A-B, c).
__device__ __forceinline__ void stage1(__half* __restrict__ Xb, int tile, int w, int lane,
                                       const int* __restrict__ gidx,
                                       const uint32_t* aC, const uint32_t* cC) {
    int ch = lane & 7, hw = lane >> 3;
    int jreg = gidx[tile * TM + w * 16 + (lane & 15)];
    int n = tile * 4 + (w >> 1);
    uint4 bu = *(const uint4*)&g_Bh[n * 32 + ch * 4];
    #pragma unroll
    for (int i = 0; i < 4; ++i) {
        int r = w * 16 + i * 4 + hw;
        int j = __shfl_sync(0xffffffffu, jreg, i * 4 + hw);
        uint4 au = *(const uint4*)&g_Ah[(size_t)j * 32 + ch * 4];
        uint4 o;
        o.x = hfma2relu(aC[0], hsub2u(au.x, bu.x), cC[0]);
        o.y = hfma2relu(aC[1], hsub2u(au.y, bu.y), cC[1]);
        o.z = hfma2relu(aC[2], hsub2u(au.z, bu.z), cC[2]);
        o.w = hfma2relu(aC[3], hsub2u(au.w, bu.w), cC[3]);
        *(uint4*)(Xb + r * 64 + ((ch ^ (r & 7)) << 3)) = o;
    }
}

// ---------------- layer1: fin0 inline; 8 warps, warp tile 32x32 ------------
__global__ void __launch_bounds__(256, 2)
k_l1(const int* __restrict__ gidx, const float* __restrict__ W1,
     const float* __restrict__ g0, const float* __restrict__ be0) {
    extern __shared__ __align__(16) __half X[];   // [2][TILEH]
    __shared__ uint32_t aHsh[32], cHsh[32];       // half2-packed BN0 coefficients
    int tid = threadIdx.x;
    if (tid < 32) {
        float inv = 1.f / (float)STOT;
        int c0i = 2 * tid, c1i = 2 * tid + 1;
        float m0 = g_sum0[c0i] * inv, m1 = g_sum0[c1i] * inv;
        float v0 = g_sq0[c0i] * inv - m0 * m0, v1 = g_sq0[c1i] * inv - m1 * m1;
        float a0 = g0[c0i] * rsqrtf(v0 + BNEPS), a1 = g0[c1i] * rsqrtf(v1 + BNEPS);
        aHsh[tid] = packh2(a0, a1);
        cHsh[tid] = packh2(fmaf(-a0, m0, be0[c0i]), fmaf(-a1, m1, be0[c1i]));
    }
    int w = tid >> 5, lane = tid & 31;
    int g = lane >> 2, t = lane & 3;
    int wm = w >> 1, wn = w & 1;
    int sub = lane >> 3, ir = lane & 7;
    int rowoff = (sub & 1) * 8 + ir;
    int csel = sub >> 1;
    uint32_t Bf[4][4][2];
    #pragma unroll
    for (int nf = 0; nf < 4; ++nf)
        #pragma unroll
        for (int kf = 0; kf < 4; ++kf) {
            int n = wn * 32 + nf * 8 + g;
            const float* wr = W1 + n * C1 + kf * 16;
            Bf[nf][kf][0] = packh2(wr[2 * t], wr[2 * t + 1]);
            Bf[nf][kf][1] = packh2(wr[8 + 2 * t], wr[8 + 2 * t + 1]);
        }
    float sum[8] = {0}, sq[8] = {0};
    __syncthreads();
    uint32_t aC[4], cC[4];
    {
        int ch = lane & 7;
        #pragma unroll
        for (int q = 0; q < 4; ++q) { aC[q] = aHsh[ch * 4 + q]; cC[q] = cHsh[ch * 4 + q]; }
    }

    int tile = blockIdx.x, buf = 0;
    stage1(X, tile, w, lane, gidx, aC, cC);
    for (; tile < NT1; tile += gridDim.x, buf ^= 1) {
        __syncthreads();
        int nxt = tile + gridDim.x;
        if (nxt < NT1) stage1(X + (buf ^ 1) * TILEH, nxt, w, lane, gidx, aC, cC);
        const __half* Xb = X + buf * TILEH;
        #pragma unroll
        for (int mf = 0; mf < 2; ++mf) {
            int rb = wm * 32 + mf * 16;
            float acc[4][4];
            #pragma unroll
            for (int nf = 0; nf < 4; ++nf)
                #pragma unroll
                for (int e = 0; e < 4; ++e) acc[nf][e] = 0.f;
            #pragma unroll
            for (int kf = 0; kf < 4; ++kf) {
                uint32_t Af[4];
                ldsm4(Af, Xb + (rb + rowoff) * 64 + (((2 * kf + csel) ^ ir) << 3));
                #pragma unroll
                for (int nf = 0; nf < 4; ++nf) mma16(acc[nf], Af, Bf[nf][kf]);
            }
            #pragma unroll
            for (int q = 0; q < 2; ++q) {
                uint4 pv;
                pv.x = packh2(acc[2 * q][0], acc[2 * q][1]);
                pv.y = packh2(acc[2 * q][2], acc[2 * q][3]);
                pv.z = packh2(acc[2 * q + 1][0], acc[2 * q + 1][1]);
                pv.w = packh2(acc[2 * q + 1][2], acc[2 * q + 1][3]);
                g_y1f[(size_t)tile * 1024 + w * 128 + mf * 64 + q * 32 + lane] = pv;
            }
            #pragma unroll
            for (int nf = 0; nf < 4; ++nf) {
                sum[nf * 2 + 0] += acc[nf][0] + acc[nf][2];
                sum[nf * 2 + 1] += acc[nf][1] + acc[nf][3];
                sq[nf * 2 + 0] += acc[nf][0] * acc[nf][0] + acc[nf][2] * acc[nf][2];
                sq[nf * 2 + 1] += acc[nf][1] * acc[nf][1] + acc[nf][3] * acc[nf][3];
            }
        }
    }
    #pragma unroll
    for (int sl = 0; sl < 8; ++sl) {
        float s = sum[sl], q = sq[sl];
        s += __shfl_xor_sync(~0u, s, 4);  q += __shfl_xor_sync(~0u, q, 4);
        s += __shfl_xor_sync(~0u, s, 8);  q += __shfl_xor_sync(~0u, q, 8);
        s += __shfl_xor_sync(~0u, s, 16); q += __shfl_xor_sync(~0u, q, 16);
        if (g == 0) {
            int col = wn * 32 + (sl >> 1) * 8 + 2 * t + (sl & 1);
            atomicAdd(&g_sum1[col], s);
            atomicAdd(&g_sq1[col], q);
        }
    }
}

// ---------------- layer2: R12-proven (cp.async ring, 64x32 tile) -----------
__global__ void __launch_bounds__(256, 2)
k_l2(const float* __restrict__ W2,
     const float* __restrict__ g1, const float* __restrict__ be1,
     const float* __restrict__ g2) {
    extern __shared__ __align__(16) uint4 Ys[];   // [S2][1024]
    __shared__ uint32_t aH[32], cH[32];           // half2-packed BN1 coefficients
    int tid = threadIdx.x;
    if (tid < 32) {
        float inv = 1.f / (float)STOT;
        int c0i = 2 * tid, c1i = 2 * tid + 1;
        float m0 = g_sum1[c0i] * inv, m1 = g_sum1[c1i] * inv;
        float v0 = g_sq1[c0i] * inv - m0 * m0, v1 = g_sq1[c1i] * inv - m1 * m1;
        float a0 = g1[c0i] * rsqrtf(v0 + BNEPS), a1 = g1[c1i] * rsqrtf(v1 + BNEPS);
        aH[tid] = packh2(a0, a1);
        cH[tid] = packh2(fmaf(-a0, m0, be1[c0i]), fmaf(-a1, m1, be1[c1i]));
    }
    int w = tid >> 5, lane = tid & 31;
    int g = lane >> 2, t = lane & 3;
    int wm = w >> 2, wn = w & 3;
    uint32_t Bf[4][4][2];
    #pragma unroll
    for (int nf = 0; nf < 4; ++nf) {
        int n = wn * 32 + nf * 8 + g;
        float s = (g2[n] < 0.f) ? -1.f : 1.f;
        #pragma unroll
        for (int kf = 0; kf < 4; ++kf) {
            const float* wr = W2 + n * C2 + kf * 16;
            Bf[nf][kf][0] = packh2(s * wr[2 * t], s * wr[2 * t + 1]);
            Bf[nf][kf][1] = packh2(s * wr[8 + 2 * t], s * wr[8 + 2 * t + 1]);
        }
    }
    float sum[8] = {0}, sq[8] = {0};
    __syncthreads();
    uint32_t aHr[4][2], cHr[4][2];
    #pragma unroll
    for (int kf = 0; kf < 4; ++kf) {
        aHr[kf][0] = aH[kf * 8 + t];     cHr[kf][0] = cH[kf * 8 + t];
        aHr[kf][1] = aH[kf * 8 + t + 4]; cHr[kf][1] = cH[kf * 8 + t + 4];
    }

    #pragma unroll
    for (int s = 0; s < S2 - 1; ++s) {
        int tl = blockIdx.x + s * gridDim.x;
        if (tl < NT1) {
            #pragma unroll
            for (int i2 = 0; i2 < 4; ++i2) {
                int u = tid + i2 * 256;
                cpa16(&Ys[s * 1024 + u], g_y1f + (size_t)tl * 1024 + u);
            }
        }
        asm volatile("cp.async.commit_group;" ::: "memory");
    }

    int it = 0;
    for (int tile = blockIdx.x; tile < NT1; tile += gridDim.x, ++it) {
        asm volatile("cp.async.wait_group %0;" :: "n"(S2 - 2));
        __syncthreads();
        int nt = tile + (S2 - 1) * gridDim.x;
        int nb = (it + S2 - 1) & (S2 - 1);
        if (nt < NT1) {
            #pragma unroll
            for (int i2 = 0; i2 < 4; ++i2) {
                int u = tid + i2 * 256;
                cpa16(&Ys[nb * 1024 + u], g_y1f + (size_t)nt * 1024 + u);
            }
        }
        asm volatile("cp.async.commit_group;" ::: "memory");

        const uint4* base = Ys + (it & (S2 - 1)) * 1024 + lane;
        float mxx[2][8];
        #pragma unroll
        for (int ps = 0; ps < 2; ++ps)
            #pragma unroll
            for (int sl = 0; sl < 8; ++sl) mxx[ps][sl] = -1e30f;
        #pragma unroll
        for (int mf = 0; mf < 4; ++mf) {
            int rb16 = wm * 4 + mf;
            int rowpart = ((rb16 >> 1) << 8) + ((rb16 & 1) << 6);
            uint4 pv[4];
            #pragma unroll
            for (int kf = 0; kf < 4; ++kf)
                pv[kf] = base[rowpart + ((kf >> 1) << 7) + ((kf & 1) << 5)];
            float acc[4][4];
            #pragma unroll
            for (int nf = 0; nf < 4; ++nf)
                #pragma unroll
                for (int e = 0; e < 4; ++e) acc[nf][e] = 0.f;
            #pragma unroll
            for (int kf = 0; kf < 4; ++kf) {
                uint32_t Af[4];
                Af[0] = hfma2relu(aHr[kf][0], pv[kf].x, cHr[kf][0]);
                Af[1] = hfma2relu(aHr[kf][0], pv[kf].y, cHr[kf][0]);
                Af[2] = hfma2relu(aHr[kf][1], pv[kf].z, cHr[kf][1]);
                Af[3] = hfma2relu(aHr[kf][1], pv[kf].w, cHr[kf][1]);
                #pragma unroll
                for (int nf = 0; nf < 4; ++nf) mma16(acc[nf], Af, Bf[nf][kf]);
            }
            int ps = mf >> 1;
            #pragma unroll
            for (int nf = 0; nf < 4; ++nf) {
                sum[nf * 2 + 0] += acc[nf][0] + acc[nf][2];
                sum[nf * 2 + 1] += acc[nf][1] + acc[nf][3];
                sq[nf * 2 + 0] += acc[nf][0] * acc[nf][0] + acc[nf][2] * acc[nf][2];
                sq[nf * 2 + 1] += acc[nf][1] * acc[nf][1] + acc[nf][3] * acc[nf][3];
                mxx[ps][nf * 2 + 0] = fmaxf(mxx[ps][nf * 2 + 0], fmaxf(acc[nf][0], acc[nf][2]));
                mxx[ps][nf * 2 + 1] = fmaxf(mxx[ps][nf * 2 + 1], fmaxf(acc[nf][1], acc[nf][3]));
            }
        }
        #pragma unroll
        for (int ps = 0; ps < 2; ++ps)
            #pragma unroll
            for (int sl = 0; sl < 8; ++sl) {
                float mx = mxx[ps][sl];
                mx = fmaxf(mx, __shfl_xor_sync(~0u, mx, 4));
                mx = fmaxf(mx, __shfl_xor_sync(~0u, mx, 8));
                mx = fmaxf(mx, __shfl_xor_sync(~0u, mx, 16));
                if (g == 0) {
                    int col = wn * 32 + (sl >> 1) * 8 + 2 * t + (sl & 1);
                    int n = tile * 4 + wm * 2 + ps;
                    g_pmax[n * C3 + col] = mx;
                }
            }
    }
    #pragma unroll
    for (int sl = 0; sl < 8; ++sl) {
        float s = sum[sl], q = sq[sl];
        s += __shfl_xor_sync(~0u, s, 4);  q += __shfl_xor_sync(~0u, q, 4);
        s += __shfl_xor_sync(~0u, s, 8);  q += __shfl_xor_sync(~0u, q, 8);
        s += __shfl_xor_sync(~0u, s, 16); q += __shfl_xor_sync(~0u, q, 16);
        if (g == 0) {
            int col = wn * 32 + (sl >> 1) * 8 + 2 * t + (sl & 1);
            if (g2[col] < 0.f) s = -s;   // un-fold sign for the true sum
            atomicAdd(&g_sum2[col], s);
            atomicAdd(&g_sq2[col], q);
        }
    }
}

// ---------------- epilogue: fin2 inline + BN2+relu on sign-folded max ------
__global__ void k_poolapply(float* __restrict__ out,
                            const float* __restrict__ g2,
                            const float* __restrict__ be2) {
    __shared__ float a2S[C3], c2S[C3];
    int tid = threadIdx.x;
    if (tid < C3) {
        float inv = 1.f / (float)STOT;
        float mean = g_sum2[tid] * inv;
        float var = g_sq2[tid] * inv - mean * mean;
        float a = g2[tid] * rsqrtf(var + BNEPS);
        a2S[tid] = fabsf(a);
        c2S[tid] = fmaf(-a, mean, be2[tid]);
    }
    __syncthreads();
    int idx = blockIdx.x * blockDim.x + tid;
    if (idx >= NPTS * (C3 / 4)) return;
    int n = idx >> 5, cg = (idx & 31) * 4;
    float4 a = *(const float4*)&a2S[cg];
    float4 c = *(const float4*)&c2S[cg];
    float4 m = *(const float4*)&g_pmax[n * C3 + cg];
    float4 o;
    o.x = fmaxf(0.f, fmaf(a.x, m.x, c.x));
    o.y = fmaxf(0.f, fmaf(a.y, m.y, c.y));
    o.z = fmaxf(0.f, fmaf(a.z, m.z, c.z));
    o.w = fmaxf(0.f, fmaf(a.w, m.w, c.w));
    *(float4*)&out[(size_t)n * C3 + cg] = o;
}

// ---------------- host entry ------------------------------------------------
extern "C" void kernel_launch(void* const* d_in, const int* in_sizes, int n_in,
                              void* d_out, int out_size) {
    const float* center  = (const float*)d_in[0];
    const float* normal  = (const float*)d_in[1];
    const float* feature = (const float*)d_in[2];
    const int*   offset  = (const int*)d_in[3];
    const int*   gidx    = (const int*)d_in[4];
    const float* W0 = (const float*)d_in[5];
    const float* b0 = (const float*)d_in[6];
    const float* g0 = (const float*)d_in[7];
    const float* be0 = (const float*)d_in[8];
    const float* W1 = (const float*)d_in[9];
    const float* g1 = (const float*)d_in[11];
    const float* be1 = (const float*)d_in[12];
    const float* W2 = (const float*)d_in[13];
    const float* g2 = (const float*)d_in[15];
    const float* be2 = (const float*)d_in[16];

    float* out = (float*)d_out;
    bool full = (out_size >= 2 * NPTS * 3 + NPTS * C3 + 1);
    float* featBase = full ? out + 2 * NPTS * 3 : out;

    const int SMX = 2 * TILEH * 2;       // 32 KB (k_l1 double buffer)
    const int SM2 = S2 * 1024 * 16;      // 64 KB (k_l2 cp.async ring)
    cudaFuncSetAttribute(k_l2, cudaFuncAttributeMaxDynamicSharedMemorySize, SM2);

    k_pre<<<296, BLK>>>(center, normal, feature, offset, W0, b0, out, full ? 1 : 0);
    k_l0stats<<<1184, BLK>>>(gidx);
    k_l1<<<296, 256, SMX>>>(gidx, W1, g0, be0);
    k_l2<<<296, 256, SM2>>>(W2, g1, be1, g2);
    k_poolapply<<<5000, BLK>>>(featBase, g2, be2);
}

// round 16
// speedup vs baseline: 1.1312x; 1.0683x over previous
#include <cuda_runtime.h>
#include <cuda_fp16.h>
#include <cstdint>

#define NPTS 40000
#define NSAMP 32
#define STOT (NPTS * NSAMP)     // 1,280,000
#define C0IN 38
#define C1 64
#define C2 64
#define C3 128
#define BNEPS 1e-5f
#define BLK 256
#define NWARP 8
#define TM 128
#define NT1 (STOT / TM)         // 10000 tiles
#define TILEH (TM * 64)         // halves per staging tile (16 KB)
#define S1 4                    // k_l1 cp.async pipeline depth
#define S2 4                    // k_l2 cp.async pipeline depth

// ---------------- scratch ---------------------------------------------------
__device__ __align__(16) __half2 g_Ah[NPTS * 32];   // per-point A (fp16)
__device__ __align__(16) __half2 g_Bh[NPTS * 32];   // per-point B (fp16)
__device__ __align__(16) uint4 g_y1f[(size_t)NT1 * 1024];   // fragment-linear fp16 y1
__device__ __align__(16) float g_pmax[NPTS * C3];           // sign-folded extrema

__device__ float g_sum0[C1], g_sq0[C1];
__device__ float g_sum1[C2], g_sq1[C2];
__device__ float g_sum2[C3], g_sq2[C3];

// ---------------- helpers ---------------------------------------------------
__device__ __forceinline__ void ldsm4(uint32_t* a, const __half* p) {
    uint32_t sa = (uint32_t)__cvta_generic_to_shared(p);
    asm volatile("ldmatrix.sync.aligned.m8n8.x4.shared.b16 {%0,%1,%2,%3}, [%4];"
                 : "=r"(a[0]), "=r"(a[1]), "=r"(a[2]), "=r"(a[3]) : "r"(sa));
}
__device__ __forceinline__ void mma16(float* d, const uint32_t* a, const uint32_t* b) {
    asm volatile(
        "mma.sync.aligned.m16n8k16.row.col.f32.f16.f16.f32 "
        "{%0,%1,%2,%3}, {%4,%5,%6,%7}, {%8,%9}, {%0,%1,%2,%3};"
        : "+f"(d[0]), "+f"(d[1]), "+f"(d[2]), "+f"(d[3])
        : "r"(a[0]), "r"(a[1]), "r"(a[2]), "r"(a[3]), "r"(b[0]), "r"(b[1]));
}
__device__ __forceinline__ uint32_t packh2(float x, float y) {
    __half2 h = __floats2half2_rn(x, y);
    return *reinterpret_cast<uint32_t*>(&h);
}
__device__ __forceinline__ uint32_t hfma2relu(uint32_t a, uint32_t y, uint32_t c) {
    __half2 r = __hfma2_relu(*reinterpret_cast<__half2*>(&a),
                             *reinterpret_cast<__half2*>(&y),
                             *reinterpret_cast<__half2*>(&c));
    return *reinterpret_cast<uint32_t*>(&r);
}
__device__ __forceinline__ uint32_t hfma2u(uint32_t a, uint32_t y, uint32_t c) {
    __half2 r = __hfma2(*reinterpret_cast<__half2*>(&a),
                        *reinterpret_cast<__half2*>(&y),
                        *reinterpret_cast<__half2*>(&c));
    return *reinterpret_cast<uint32_t*>(&r);
}
__device__ __forceinline__ void cpa16(void* dst, const void* src) {
    uint32_t d = (uint32_t)__cvta_generic_to_shared(dst);
    asm volatile("cp.async.cg.shared.global [%0], [%1], 16;" :: "r"(d), "l"(src) : "memory");
}

// ---------------- k_pre: zero stats + passthrough copy + A/B precompute ----
__global__ void k_pre(const float* __restrict__ center,
                      const float* __restrict__ normal,
                      const float* __restrict__ feature,
                      const int* __restrict__ offset,
                      const float* __restrict__ W0,
                      const float* __restrict__ b0,
                      float* __restrict__ out, int doCopy) {
    if (blockIdx.x == 0) {
        int t = threadIdx.x;
        if (t < C1) { g_sum0[t] = 0.f; g_sq0[t] = 0.f; g_sum1[t] = 0.f; g_sq1[t] = 0.f; }
        if (t < C3) { g_sum2[t] = 0.f; g_sq2[t] = 0.f; }
    }
    if (doCopy) {
        int i = blockIdx.x * blockDim.x + threadIdx.x;
        int stride = gridDim.x * blockDim.x;
        for (; i < 2 * NPTS * 3; i += stride) {
            out[i] = (i < NPTS * 3) ? center[i] : normal[i - NPTS * 3];
        }
        if (blockIdx.x == 0 && threadIdx.x == 0) {
            out[2 * NPTS * 3 + NPTS * C3] = (float)offset[0];
        }
    }

    __shared__ __align__(16) float Wt[C0IN * C1];
    __shared__ float xs[NWARP][C0IN];
    int tid = threadIdx.x;
    for (int i = tid; i < C0IN * C1; i += BLK) {
        int o = i / C0IN, c = i % C0IN;
        Wt[c * C1 + o] = W0[i];
    }
    __syncthreads();
    int w = tid >> 5, lane = tid & 31;
    int o0 = 2 * lane;
    float bias0 = b0[o0], bias1 = b0[o0 + 1];
    int wg = blockIdx.x * NWARP + w, nW = gridDim.x * NWARP;
    for (int n = wg; n < NPTS; n += nW) {
        {
            float v;
            if (lane < 3)      v = center[n * 3 + lane];
            else if (lane < 6) v = normal[n * 3 + lane - 3];
            else               v = feature[n * 32 + lane - 6];
            xs[w][lane] = v;
            if (lane < C0IN - 32) xs[w][32 + lane] = feature[n * 32 + 26 + lane];
        }
        __syncwarp();
        float a0 = 0.f, a1 = 0.f, bp0 = 0.f, bp1 = 0.f;
        #pragma unroll
        for (int c = 0; c < C0IN; ++c) {
            float2 wv = *(const float2*)&Wt[c * C1 + o0];
            float x = xs[w][c];
            a0 += wv.x * x; a1 += wv.y * x;
            if (c < 3) { bp0 += wv.x * x; bp1 += wv.y * x; }
        }
        g_Ah[n * 32 + lane] = __floats2half2_rn(a0 + bias0, a1 + bias1);
        g_Bh[n * 32 + lane] = __floats2half2_rn(bp0, bp1);
        __syncwarp();
    }
}

// ---------------- layer-0 stats on fp16 A/B --------------------------------
__global__ void k_l0stats(const int* __restrict__ gidx) {
    __shared__ float sS[C1], sQ[C1];
    int tid = threadIdx.x;
    if (tid < C1) { sS[tid] = 0.f; sQ[tid] = 0.f; }
    __syncthreads();
    int w = tid >> 5, lane = tid & 31;
    float s0 = 0.f, s1 = 0.f, q0 = 0.f, q1 = 0.f;
    int wg = blockIdx.x * NWARP + w, nW = gridDim.x * NWARP;
    for (int n = wg; n < NPTS; n += nW) {
        float2 bv = __half22float2(g_Bh[n * 32 + lane]);
        int js = gidx[n * NSAMP + lane];
        #pragma unroll
        for (int s = 0; s < NSAMP; ++s) {
            int j = __shfl_sync(0xffffffffu, js, s);
            float2 av = __half22float2(g_Ah[j * 32 + lane]);
            float y0 = av.x - bv.x, y1v = av.y - bv.y;
            s0 += y0; s1 += y1v; q0 += y0 * y0; q1 += y1v * y1v;
        }
    }
    int c0 = 2 * lane;
    atomicAdd(&sS[c0], s0); atomicAdd(&sS[c0 + 1], s1);
    atomicAdd(&sQ[c0], q0); atomicAdd(&sQ[c0 + 1], q1);
    __syncthreads();
    if (tid < C1) { atomicAdd(&g_sum0[tid], sS[tid]); atomicAdd(&g_sq0[tid], sQ[tid]); }
}

// ---------------- layer1: cp.async raw-A gather ring, BN0 in fragments -----
// x1 = relu(a0*A + d),  d[n][col] = c0[col] - a0[col]*B[n][col]  (per warp-point)
__global__ void __launch_bounds__(256, 2)
k_l1(const int* __restrict__ gidx, const float* __restrict__ W1,
     const float* __restrict__ g0, const float* __restrict__ be0) {
    extern __shared__ __align__(16) __half X[];   // [S1][TILEH]
    __shared__ uint32_t aHsh[32], cHsh[32], naHsh[32];
    __shared__ uint32_t dS[S1][128];              // per-tile d, 4 points x 32 colpairs
    int tid = threadIdx.x;
    if (tid < 32) {
        float inv = 1.f / (float)STOT;
        int c0i = 2 * tid, c1i = 2 * tid + 1;
        float m0 = g_sum0[c0i] * inv, m1 = g_sum0[c1i] * inv;
        float v0 = g_sq0[c0i] * inv - m0 * m0, v1 = g_sq0[c1i] * inv - m1 * m1;
        float a0 = g0[c0i] * rsqrtf(v0 + BNEPS), a1 = g0[c1i] * rsqrtf(v1 + BNEPS);
        aHsh[tid] = packh2(a0, a1);
        naHsh[tid] = packh2(-a0, -a1);
        cHsh[tid] = packh2(fmaf(-a0, m0, be0[c0i]), fmaf(-a1, m1, be0[c1i]));
    }
    int w = tid >> 5, lane = tid & 31;
    int g = lane >> 2, t = lane & 3;
    int wm = w >> 1, wn = w & 1;
    int sub = lane >> 3, ir = lane & 7;
    int rowoff = (sub & 1) * 8 + ir;
    int csel = sub >> 1;
    uint32_t Bf[4][4][2];
    #pragma unroll
    for (int nf = 0; nf < 4; ++nf)
        #pragma unroll
        for (int kf = 0; kf < 4; ++kf) {
            int n = wn * 32 + nf * 8 + g;
            const float* wr = W1 + n * C1 + kf * 16;
            Bf[nf][kf][0] = packh2(wr[2 * t], wr[2 * t + 1]);
            Bf[nf][kf][1] = packh2(wr[8 + 2 * t], wr[8 + 2 * t + 1]);
        }
    float sum[8] = {0}, sq[8] = {0};
    __syncthreads();
    uint32_t aHr[4][2];
    #pragma unroll
    for (int kf = 0; kf < 4; ++kf) {
        aHr[kf][0] = aHsh[kf * 8 + t];
        aHr[kf][1] = aHsh[kf * 8 + t + 4];
    }
    int srow = tid >> 3, sch = tid & 7;           // staging: 8 chunks per row

    // issue helper (inlined twice)
    #define L1_ISSUE(TL, NB)                                                        \
        if ((TL) < NT1) {                                                           \
            _Pragma("unroll")                                                       \
            for (int i2 = 0; i2 < 4; ++i2) {                                        \
                int r = srow + i2 * 32;                                             \
                int j = gidx[(TL) * TM + r];                                        \
                cpa16(X + (NB) * TILEH + r * 64 + ((sch ^ (r & 7)) << 3),           \
                      &g_Ah[(size_t)j * 32 + sch * 4]);                             \
            }                                                                       \
            if (tid < 128) {                                                        \
                int pt = tid >> 5, cp = tid & 31;                                   \
                uint32_t bb = *(const uint32_t*)&g_Bh[((TL) * 4 + pt) * 32 + cp];   \
                dS[NB][tid] = hfma2u(naHsh[cp], bb, cHsh[cp]);                      \
            }                                                                       \
        }                                                                           \
        asm volatile("cp.async.commit_group;" ::: "memory");

    #pragma unroll
    for (int s = 0; s < S1 - 1; ++s) {
        int tl = blockIdx.x + s * gridDim.x;
        L1_ISSUE(tl, s)
    }

    int it = 0;
    for (int tile = blockIdx.x; tile < NT1; tile += gridDim.x, ++it) {
        asm volatile("cp.async.wait_group %0;" :: "n"(S1 - 2));
        __syncthreads();
        int nt = tile + (S1 - 1) * gridDim.x;
        int nb = (it + S1 - 1) & (S1 - 1);
        L1_ISSUE(nt, nb)

        int cb = it & (S1 - 1);
        const __half* Xb = X + cb * TILEH;
        const uint32_t* drow = dS[cb] + wm * 32;
        uint32_t dr[4][2];
        #pragma unroll
        for (int kf = 0; kf < 4; ++kf) {
            dr[kf][0] = drow[kf * 8 + t];
            dr[kf][1] = drow[kf * 8 + t + 4];
        }
        #pragma unroll
        for (int mf = 0; mf < 2; ++mf) {
            int rb = wm * 32 + mf * 16;
            float acc[4][4];
            #pragma unroll
            for (int nf = 0; nf < 4; ++nf)
                #pragma unroll
                for (int e = 0; e < 4; ++e) acc[nf][e] = 0.f;
            #pragma unroll
            for (int kf = 0; kf < 4; ++kf) {
                uint32_t Af[4];
                ldsm4(Af, Xb + (rb + rowoff) * 64 + (((2 * kf + csel) ^ ir) << 3));
                Af[0] = hfma2relu(aHr[kf][0], Af[0], dr[kf][0]);
                Af[1] = hfma2relu(aHr[kf][0], Af[1], dr[kf][0]);
                Af[2] = hfma2relu(aHr[kf][1], Af[2], dr[kf][1]);
                Af[3] = hfma2relu(aHr[kf][1], Af[3], dr[kf][1]);
                #pragma unroll
                for (int nf = 0; nf < 4; ++nf) mma16(acc[nf], Af, Bf[nf][kf]);
            }
            #pragma unroll
            for (int q = 0; q < 2; ++q) {
                uint4 pv;
                pv.x = packh2(acc[2 * q][0], acc[2 * q][1]);
                pv.y = packh2(acc[2 * q][2], acc[2 * q][3]);
                pv.z = packh2(acc[2 * q + 1][0], acc[2 * q + 1][1]);
                pv.w = packh2(acc[2 * q + 1][2], acc[2 * q + 1][3]);
                g_y1f[(size_t)tile * 1024 + w * 128 + mf * 64 + q * 32 + lane] = pv;
            }
            #pragma unroll
            for (int nf = 0; nf < 4; ++nf) {
                sum[nf * 2 + 0] += acc[nf][0] + acc[nf][2];
                sum[nf * 2 + 1] += acc[nf][1] + acc[nf][3];
                sq[nf * 2 + 0] += acc[nf][0] * acc[nf][0] + acc[nf][2] * acc[nf][2];
                sq[nf * 2 + 1] += acc[nf][1] * acc[nf][1] + acc[nf][3] * acc[nf][3];
            }
        }
    }
    #pragma unroll
    for (int sl = 0; sl < 8; ++sl) {
        float s = sum[sl], q = sq[sl];
        s += __shfl_xor_sync(~0u, s, 4);  q += __shfl_xor_sync(~0u, q, 4);
        s += __shfl_xor_sync(~0u, s, 8);  q += __shfl_xor_sync(~0u, q, 8);
        s += __shfl_xor_sync(~0u, s, 16); q += __shfl_xor_sync(~0u, q, 16);
        if (g == 0) {
            int col = wn * 32 + (sl >> 1) * 8 + 2 * t + (sl & 1);
            atomicAdd(&g_sum1[col], s);
            atomicAdd(&g_sq1[col], q);
        }
    }
    #undef L1_ISSUE
}

// ---------------- layer2: R12-proven (cp.async ring, 64x32 tile) -----------
__global__ void __launch_bounds__(256, 2)
k_l2(const float* __restrict__ W2,
     const float* __restrict__ g1, const float* __restrict__ be1,
     const float* __restrict__ g2) {
    extern __shared__ __align__(16) uint4 Ys[];   // [S2][1024]
    __shared__ uint32_t aH[32], cH[32];           // half2-packed BN1 coefficients
    int tid = threadIdx.x;
    if (tid < 32) {
        float inv = 1.f / (float)STOT;
        int c0i = 2 * tid, c1i = 2 * tid + 1;
        float m0 = g_sum1[c0i] * inv, m1 = g_sum1[c1i] * inv;
        float v0 = g_sq1[c0i] * inv - m0 * m0, v1 = g_sq1[c1i] * inv - m1 * m1;
        float a0 = g1[c0i] * rsqrtf(v0 + BNEPS), a1 = g1[c1i] * rsqrtf(v1 + BNEPS);
        aH[tid] = packh2(a0, a1);
        cH[tid] = packh2(fmaf(-a0, m0, be1[c0i]), fmaf(-a1, m1, be1[c1i]));
    }
    int w = tid >> 5, lane = tid & 31;
    int g = lane >> 2, t = lane & 3;
    int wm = w >> 2, wn = w & 3;
    uint32_t Bf[4][4][2];
    #pragma unroll
    for (int nf = 0; nf < 4; ++nf) {
        int n = wn * 32 + nf * 8 + g;
        float s = (g2[n] < 0.f) ? -1.f : 1.f;
        #pragma unroll
        for (int kf = 0; kf < 4; ++kf) {
            const float* wr = W2 + n * C2 + kf * 16;
            Bf[nf][kf][0] = packh2(s * wr[2 * t], s * wr[2 * t + 1]);
            Bf[nf][kf][1] = packh2(s * wr[8 + 2 * t], s * wr[8 + 2 * t + 1]);
        }
    }
    float sum[8] = {0}, sq[8] = {0};
    __syncthreads();
    uint32_t aHr[4][2], cHr[4][2];
    #pragma unroll
    for (int kf = 0; kf < 4; ++kf) {
        aHr[kf][0] = aH[kf * 8 + t];     cHr[kf][0] = cH[kf * 8 + t];
        aHr[kf][1] = aH[kf * 8 + t + 4]; cHr[kf][1] = cH[kf * 8 + t + 4];
    }

    #pragma unroll
    for (int s = 0; s < S2 - 1; ++s) {
        int tl = blockIdx.x + s * gridDim.x;
        if (tl < NT1) {
            #pragma unroll
            for (int i2 = 0; i2 < 4; ++i2) {
                int u = tid + i2 * 256;
                cpa16(&Ys[s * 1024 + u], g_y1f + (size_t)tl * 1024 + u);
            }
        }
        asm volatile("cp.async.commit_group;" ::: "memory");
    }

    int it = 0;
    for (int tile = blockIdx.x; tile < NT1; tile += gridDim.x, ++it) {
        asm volatile("cp.async.wait_group %0;" :: "n"(S2 - 2));
        __syncthreads();
        int nt = tile + (S2 - 1) * gridDim.x;
        int nb = (it + S2 - 1) & (S2 - 1);
        if (nt < NT1) {
            #pragma unroll
            for (int i2 = 0; i2 < 4; ++i2) {
                int u = tid + i2 * 256;
                cpa16(&Ys[nb * 1024 + u], g_y1f + (size_t)nt * 1024 + u);
            }
        }
        asm volatile("cp.async.commit_group;" ::: "memory");

        const uint4* base = Ys + (it & (S2 - 1)) * 1024 + lane;
        float mxx[2][8];
        #pragma unroll
        for (int ps = 0; ps < 2; ++ps)
            #pragma unroll
            for (int sl = 0; sl < 8; ++sl) mxx[ps][sl] = -1e30f;
        #pragma unroll
        for (int mf = 0; mf < 4; ++mf) {
            int rb16 = wm * 4 + mf;
            int rowpart = ((rb16 >> 1) << 8) + ((rb16 & 1) << 6);
            uint4 pv[4];
            #pragma unroll
            for (int kf = 0; kf < 4; ++kf)
                pv[kf] = base[rowpart + ((kf >> 1) << 7) + ((kf & 1) << 5)];
            float acc[4][4];
            #pragma unroll
            for (int nf = 0; nf < 4; ++nf)
                #pragma unroll
                for (int e = 0; e < 4; ++e) acc[nf][e] = 0.f;
            #pragma unroll
            for (int kf = 0; kf < 4; ++kf) {
                uint32_t Af[4];
                Af[0] = hfma2relu(aHr[kf][0], pv[kf].x, cHr[kf][0]);
                Af[1] = hfma2relu(aHr[kf][0], pv[kf].y, cHr[kf][0]);
                Af[2] = hfma2relu(aHr[kf][1], pv[kf].z, cHr[kf][1]);
                Af[3] = hfma2relu(aHr[kf][1], pv[kf].w, cHr[kf][1]);
                #pragma unroll
                for (int nf = 0; nf < 4; ++nf) mma16(acc[nf], Af, Bf[nf][kf]);
            }
            int ps = mf >> 1;
            #pragma unroll
            for (int nf = 0; nf < 4; ++nf) {
                sum[nf * 2 + 0] += acc[nf][0] + acc[nf][2];
                sum[nf * 2 + 1] += acc[nf][1] + acc[nf][3];
                sq[nf * 2 + 0] += acc[nf][0] * acc[nf][0] + acc[nf][2] * acc[nf][2];
                sq[nf * 2 + 1] += acc[nf][1] * acc[nf][1] + acc[nf][3] * acc[nf][3];
                mxx[ps][nf * 2 + 0] = fmaxf(mxx[ps][nf * 2 + 0], fmaxf(acc[nf][0], acc[nf][2]));
                mxx[ps][nf * 2 + 1] = fmaxf(mxx[ps][nf * 2 + 1], fmaxf(acc[nf][1], acc[nf][3]));
            }
        }
        #pragma unroll
        for (int ps = 0; ps < 2; ++ps)
            #pragma unroll
            for (int sl = 0; sl < 8; ++sl) {
                float mx = mxx[ps][sl];
                mx = fmaxf(mx, __shfl_xor_sync(~0u, mx, 4));
                mx = fmaxf(mx, __shfl_xor_sync(~0u, mx, 8));
                mx = fmaxf(mx, __shfl_xor_sync(~0u, mx, 16));
                if (g == 0) {
                    int col = wn * 32 + (sl >> 1) * 8 + 2 * t + (sl & 1);
                    int n = tile * 4 + wm * 2 + ps;
                    g_pmax[n * C3 + col] = mx;
                }
            }
    }
    #pragma unroll
    for (int sl = 0; sl < 8; ++sl) {
        float s = sum[sl], q = sq[sl];
        s += __shfl_xor_sync(~0u, s, 4);  q += __shfl_xor_sync(~0u, q, 4);
        s += __shfl_xor_sync(~0u, s, 8);  q += __shfl_xor_sync(~0u, q, 8);
        s += __shfl_xor_sync(~0u, s, 16); q += __shfl_xor_sync(~0u, q, 16);
        if (g == 0) {
            int col = wn * 32 + (sl >> 1) * 8 + 2 * t + (sl & 1);
            if (g2[col] < 0.f) s = -s;   // un-fold sign for the true sum
            atomicAdd(&g_sum2[col], s);
            atomicAdd(&g_sq2[col], q);
        }
    }
}

// ---------------- epilogue: fin2 inline + BN2+relu on sign-folded max ------
__global__ void k_poolapply(float* __restrict__ out,
                            const float* __restrict__ g2,
                            const float* __restrict__ be2) {
    __shared__ float a2S[C3], c2S[C3];
    int tid = threadIdx.x;
    if (tid < C3) {
        float inv = 1.f / (float)STOT;
        float mean = g_sum2[tid] * inv;
        float var = g_sq2[tid] * inv - mean * mean;
        float a = g2[tid] * rsqrtf(var + BNEPS);
        a2S[tid] = fabsf(a);
        c2S[tid] = fmaf(-a, mean, be2[tid]);
    }
    __syncthreads();
    int idx = blockIdx.x * blockDim.x + tid;
    if (idx >= NPTS * (C3 / 4)) return;
    int n = idx >> 5, cg = (idx & 31) * 4;
    float4 a = *(const float4*)&a2S[cg];
    float4 c = *(const float4*)&c2S[cg];
    float4 m = *(const float4*)&g_pmax[n * C3 + cg];
    float4 o;
    o.x = fmaxf(0.f, fmaf(a.x, m.x, c.x));
    o.y = fmaxf(0.f, fmaf(a.y, m.y, c.y));
    o.z = fmaxf(0.f, fmaf(a.z, m.z, c.z));
    o.w = fmaxf(0.f, fmaf(a.w, m.w, c.w));
    *(float4*)&out[(size_t)n * C3 + cg] = o;
}

// ---------------- host entry ------------------------------------------------
extern "C" void kernel_launch(void* const* d_in, const int* in_sizes, int n_in,
                              void* d_out, int out_size) {
    const float* center  = (const float*)d_in[0];
    const float* normal  = (const float*)d_in[1];
    const float* feature = (const float*)d_in[2];
    const int*   offset  = (const int*)d_in[3];
    const int*   gidx    = (const int*)d_in[4];
    const float* W0 = (const float*)d_in[5];
    const float* b0 = (const float*)d_in[6];
    const float* g0 = (const float*)d_in[7];
    const float* be0 = (const float*)d_in[8];
    const float* W1 = (const float*)d_in[9];
    const float* g1 = (const float*)d_in[11];
    const float* be1 = (const float*)d_in[12];
    const float* W2 = (const float*)d_in[13];
    const float* g2 = (const float*)d_in[15];
    const float* be2 = (const float*)d_in[16];

    float* out = (float*)d_out;
    bool full = (out_size >= 2 * NPTS * 3 + NPTS * C3 + 1);
    float* featBase = full ? out + 2 * NPTS * 3 : out;

    const int SM1 = S1 * TILEH * 2;      // 64 KB (k_l1 cp.async ring)
    const int SM2 = S2 * 1024 * 16;      // 64 KB (k_l2 cp.async ring)
    cudaFuncSetAttribute(k_l1, cudaFuncAttributeMaxDynamicSharedMemorySize, SM1);
    cudaFuncSetAttribute(k_l2, cudaFuncAttributeMaxDynamicSharedMemorySize, SM2);

    k_pre<<<296, BLK>>>(center, normal, feature, offset, W0, b0, out, full ? 1 : 0);
    k_l0stats<<<1184, BLK>>>(gidx);
    k_l1<<<296, 256, SM1>>>(gidx, W1, g0, be0);
    k_l2<<<296, 256, SM2>>>(W2, g1, be1, g2);
    k_poolapply<<<5000, BLK>>>(featBase, g2, be2);
}